// round 1
// baseline (speedup 1.0000x reference)
#include <cuda_runtime.h>

#define HW   36864      // 192*192
#define SIMG 37249      // 193*193
#define NB   6

// -------- scratch (static device globals: allocation-guard safe) --------
__device__ float g_x [NB*64*HW];     // x = [ctx ; extra], (b,c,y,px)
__device__ float g_S1[NB*64*SIMG];   // integral image of x
__device__ float g_S2[NB*64*SIMG];   // integral image of x*x

// -------- packed fp32x2 helpers (Blackwell fma.rn.f32x2) --------
__device__ __forceinline__ unsigned long long pk2(float lo, float hi) {
    unsigned long long r;
    asm("mov.b64 %0, {%1, %2};" : "=l"(r) : "f"(lo), "f"(hi));
    return r;
}
__device__ __forceinline__ void fma2(unsigned long long &d,
                                     unsigned long long a,
                                     unsigned long long b) {
    asm("fma.rn.f32x2 %0, %1, %2, %0;" : "+l"(d) : "l"(a), "l"(b));
}

// ============================================================================
// K1: build x = [W_ctx @ feature + b_ctx ; extra], write g_x,
//     and out0 = W1 @ x + b1 into output channels [0,68).
// One CTA per (y,b) row. 288 threads.
// ============================================================================
__global__ __launch_bounds__(288, 2) void k1_kernel(
    const float* __restrict__ feature, const float* __restrict__ extra,
    const float* __restrict__ w_ctx,   const float* __restrict__ b_ctx,
    const float* __restrict__ w1,      const float* __restrict__ b1,
    float* __restrict__ out)
{
    extern __shared__ float sm[];
    float* s_wc = sm;            // 1024   : wcT[k*32+o]
    float* s_w1 = sm + 1024;     // 4608   : w1T[k*72+o], o padded 68->72
    float* s_f  = sm + 5632;     // 6144   : feature row [32][192]
    float* s_x  = sm + 11776;    // 12288  : x row [64][192]
    const int tid = threadIdx.x;
    const int y = blockIdx.x, b = blockIdx.y;
    const int fb = b / 3;        // jnp.repeat(...,3,axis=0): [b0,b0,b0,b1,b1,b1]

    for (int idx = tid; idx < 1024; idx += 288) {
        int o = idx >> 5, k = idx & 31;
        s_wc[k*32 + o] = w_ctx[idx];
    }
    for (int idx = tid; idx < 72*64; idx += 288) {
        int o = idx >> 6, k = idx & 63;
        s_w1[k*72 + o] = (o < 68) ? w1[o*64 + k] : 0.f;
    }
    const float* fbase = feature + (fb*32)*HW + y*192;
    const float* ebase = extra   + (b*32)*HW + y*192;
    for (int idx = tid; idx < 32*192; idx += 288) {
        int c = idx / 192, px = idx - c*192;
        s_f[idx]              = fbase[c*HW + px];
        s_x[(32+c)*192 + px]  = ebase[c*HW + px];
    }
    __syncthreads();

    // ctx GEMM: 32 out x 192 px, K=32 (256 threads: 2 out x 12 px each)
    if (tid < 256) {
        const int og = tid >> 4, pg = tid & 15;
        const int o0 = og*2, pxb = pg*12;
        unsigned long long acc[2][6];
        {
            unsigned long long p0 = pk2(b_ctx[o0],   b_ctx[o0]);
            unsigned long long p1 = pk2(b_ctx[o0+1], b_ctx[o0+1]);
            #pragma unroll
            for (int j = 0; j < 6; j++) { acc[0][j] = p0; acc[1][j] = p1; }
        }
        #pragma unroll 4
        for (int k = 0; k < 32; k++) {
            float wa = s_wc[k*32 + o0], wb = s_wc[k*32 + o0 + 1];
            unsigned long long wpa = pk2(wa, wa), wpb = pk2(wb, wb);
            #pragma unroll
            for (int j = 0; j < 6; j++) {
                unsigned long long m =
                    *(const unsigned long long*)(s_f + k*192 + pxb + 2*j);
                fma2(acc[0][j], wpa, m);
                fma2(acc[1][j], wpb, m);
            }
        }
        #pragma unroll
        for (int j = 0; j < 6; j++) {
            *(unsigned long long*)(s_x + o0*192     + pxb + 2*j) = acc[0][j];
            *(unsigned long long*)(s_x + (o0+1)*192 + pxb + 2*j) = acc[1][j];
        }
    }
    __syncthreads();

    // write x row to global
    {
        float* gx = g_x + (b*64)*HW + y*192;
        for (int idx = tid; idx < 64*96; idx += 288) {
            int c = idx / 96, pp = (idx - c*96)*2;
            *(unsigned long long*)(gx + c*HW + pp) =
                *(const unsigned long long*)(s_x + c*192 + pp);
        }
    }

    // out0 GEMM: 72(pad) out x 192 px, K=64 (288 threads: 4 out x 12 px each)
    {
        const int og = tid >> 4, pg = tid & 15;   // og 0..17
        const int o0 = og*4, pxb = pg*12;
        unsigned long long acc[4][6];
        #pragma unroll
        for (int i = 0; i < 4; i++) {
            int o = o0 + i;
            float bb = (o < 68) ? b1[o] : 0.f;
            unsigned long long p = pk2(bb, bb);
            #pragma unroll
            for (int j = 0; j < 6; j++) acc[i][j] = p;
        }
        #pragma unroll 2
        for (int k = 0; k < 64; k++) {
            float4 w4 = *(const float4*)(s_w1 + k*72 + o0);
            unsigned long long w0 = pk2(w4.x, w4.x), wA = pk2(w4.y, w4.y);
            unsigned long long w2 = pk2(w4.z, w4.z), w3 = pk2(w4.w, w4.w);
            #pragma unroll
            for (int j = 0; j < 6; j++) {
                unsigned long long m =
                    *(const unsigned long long*)(s_x + k*192 + pxb + 2*j);
                fma2(acc[0][j], w0, m);
                fma2(acc[1][j], wA, m);
                fma2(acc[2][j], w2, m);
                fma2(acc[3][j], w3, m);
            }
        }
        #pragma unroll
        for (int i = 0; i < 4; i++) {
            int o = o0 + i;
            if (o < 68) {
                float* op = out + (b*260 + o)*HW + y*192 + pxb;
                #pragma unroll
                for (int j = 0; j < 6; j++)
                    *(unsigned long long*)(op + 2*j) = acc[i][j];
            }
        }
    }
}

// ============================================================================
// K2: per-row prefix sums of x and x*x into S1,S2 rows [y+1], with left pad.
// One warp per row, 8 warps per CTA.
// ============================================================================
__global__ void k2_kernel()
{
    const int warp = threadIdx.x >> 5, lane = threadIdx.x & 31;
    const int row  = blockIdx.x * 8 + warp;        // < 6*64*192 = 73728
    const int img  = row / 192, y = row - img*192;
    const float* xr = g_x + row*192;

    float s1p[6], s2p[6];
    float a1 = 0.f, a2 = 0.f;
    #pragma unroll
    for (int j = 0; j < 6; j++) {
        float v = xr[lane*6 + j];
        a1 += v;      s1p[j] = a1;
        a2 += v * v;  s2p[j] = a2;
    }
    float t1 = a1, t2 = a2;
    #pragma unroll
    for (int off = 1; off < 32; off <<= 1) {
        float n1 = __shfl_up_sync(0xffffffffu, t1, off);
        float n2 = __shfl_up_sync(0xffffffffu, t2, off);
        if (lane >= off) { t1 += n1; t2 += n2; }
    }
    float e1 = __shfl_up_sync(0xffffffffu, t1, 1);
    float e2 = __shfl_up_sync(0xffffffffu, t2, 1);
    if (lane == 0) { e1 = 0.f; e2 = 0.f; }

    float* S1r = g_S1 + img*SIMG + (y+1)*193;
    float* S2r = g_S2 + img*SIMG + (y+1)*193;
    if (lane == 0) { S1r[0] = 0.f; S2r[0] = 0.f; }
    #pragma unroll
    for (int j = 0; j < 6; j++) {
        S1r[1 + lane*6 + j] = e1 + s1p[j];
        S2r[1 + lane*6 + j] = e2 + s2p[j];
    }
    if (y == 0) {  // zero pad row 0
        float* Z1 = g_S1 + img*SIMG;
        float* Z2 = g_S2 + img*SIMG;
        for (int j = lane; j < 193; j += 32) { Z1[j] = 0.f; Z2[j] = 0.f; }
    }
}

// ============================================================================
// K3: in-place column accumulation -> full 2D integral images.
// One CTA per (image, array). Thread owns one column; software-pipelined.
// ============================================================================
__global__ void k3_kernel()
{
    const int img = blockIdx.x;
    float* S = ((blockIdx.y == 0) ? g_S1 : g_S2) + img*SIMG;
    const int t = threadIdx.x;
    if (t >= 193) return;
    float s = 0.f;
    float v[8];
    #pragma unroll
    for (int j = 0; j < 8; j++) v[j] = S[(1 + j)*193 + t];
    for (int r0 = 1; r0 <= 192; r0 += 8) {
        float w[8];
        if (r0 + 8 <= 192) {
            #pragma unroll
            for (int j = 0; j < 8; j++) w[j] = S[(r0 + 8 + j)*193 + t];
        }
        #pragma unroll
        for (int j = 0; j < 8; j++) { s += v[j]; S[(r0 + j)*193 + t] = s; }
        #pragma unroll
        for (int j = 0; j < 8; j++) v[j] = w[j];
    }
}

// ============================================================================
// K4: per (scale, b, row, 96-px tile):
//   Phase A (warp-parallel): mean/var for 64 channels via row-difference
//     buffers D = S[y1]-S[y0] (2 rows/channel instead of 8 gathers/pixel),
//     next-channel loads prefetched; only warp-scope syncs.
//   Phase B: [64 x 128] @ [128 x 96] GEMM from smem with fma.rn.f32x2
//     (2 pixels per instruction), bias pre-loaded, packed 8B stores.
// ============================================================================
__global__ __launch_bounds__(256, 2) void k4_kernel(
    const float* __restrict__ ws0, const float* __restrict__ bs0,
    const float* __restrict__ ws1, const float* __restrict__ bs1,
    const float* __restrict__ ws2, const float* __restrict__ bs2,
    float* __restrict__ out)
{
    extern __shared__ float sm[];
    float* s_w = sm;           // 8192  : wT[k*64+o], k = 0..63 mean, 64..127 var
    float* s_m = sm + 8192;    // 12288 : [128 ch][96 px] mean/var
    float* s_d = sm + 20480;   // 2048  : per-warp D1/D2 row-diff buffers
    const int tid = threadIdx.x, warp = tid >> 5, lane = tid & 31;
    const int px0 = blockIdx.x * 96;
    const int y = blockIdx.y;
    const int z = blockIdx.z;
    const int scale = z / 6, b = z - scale*6;
    const int half = (scale == 0) ? 2 : (scale == 1) ? 4 : 8;
    const float* ws = (scale == 0) ? ws0 : (scale == 1) ? ws1 : ws2;
    const float* bs = (scale == 0) ? bs0 : (scale == 1) ? bs1 : bs2;

    for (int idx = tid; idx < 8192; idx += 256) {
        int o = idx >> 7, k = idx & 127;
        s_w[k*64 + o] = ws[idx];
    }

    const int y0 = max(y - half, 0);
    const int y1 = min(y + 1 + half, 192);
    const int c0 = max(px0 - half, 0);
    const int c1 = min(px0 + 96 + half, 192);
    const int nseg = c1 - c0 + 1;     // <= 105
    const float hh = (float)(y1 - y0);

    float inva[3];
    #pragma unroll
    for (int q = 0; q < 3; q++) {
        int gpx = px0 + lane + 32*q;
        int x0 = max(gpx - half, 0), x1 = min(gpx + 1 + half, 192);
        inva[q] = 1.0f / (hh * (float)(x1 - x0));
    }

    float* D1 = s_d + warp * 256;
    float* D2 = D1 + 128;
    const float* S1c = g_S1 + (b*64 + warp*8)*SIMG;
    const float* S2c = g_S2 + (b*64 + warp*8)*SIMG;
    const int offA = y0*193 + c0, offB = y1*193 + c0;

    float r1a[4], r1b[4], r2a[4], r2b[4];
    #pragma unroll
    for (int jj = 0; jj < 4; jj++) {
        int j = lane + 32*jj;
        bool ok = j < nseg;
        r1a[jj] = ok ? S1c[offA + j] : 0.f;
        r1b[jj] = ok ? S1c[offB + j] : 0.f;
        r2a[jj] = ok ? S2c[offA + j] : 0.f;
        r2b[jj] = ok ? S2c[offB + j] : 0.f;
    }

    for (int i = 0; i < 8; i++) {
        const int c = warp*8 + i;
        #pragma unroll
        for (int jj = 0; jj < 4; jj++) {
            int j = lane + 32*jj;
            if (j < nseg) {
                D1[j] = r1b[jj] - r1a[jj];
                D2[j] = r2b[jj] - r2a[jj];
            }
        }
        __syncwarp();
        if (i < 7) {  // prefetch next channel while this one is consumed
            const float* n1 = S1c + (i+1)*SIMG;
            const float* n2 = S2c + (i+1)*SIMG;
            #pragma unroll
            for (int jj = 0; jj < 4; jj++) {
                int j = lane + 32*jj;
                if (j < nseg) {
                    r1a[jj] = n1[offA + j]; r1b[jj] = n1[offB + j];
                    r2a[jj] = n2[offA + j]; r2b[jj] = n2[offB + j];
                }
            }
        }
        #pragma unroll
        for (int q = 0; q < 3; q++) {
            int px  = lane + 32*q;
            int gpx = px0 + px;
            int i0 = max(gpx - half, 0) - c0;
            int i1 = min(gpx + 1 + half, 192) - c0;
            float s1 = D1[i1] - D1[i0];
            float s2 = D2[i1] - D2[i0];
            float m = s1 * inva[q];
            float v = s2 * inva[q] - m*m;
            s_m[c*96 + px]      = m;
            s_m[(64+c)*96 + px] = v;
        }
        __syncwarp();
    }
    __syncthreads();

    // Phase B: 64 out x 96 px, K=128; thread tile 4 out x 6 px (3 f32x2 pairs)
    const int og = tid >> 4, pg = tid & 15;
    const int o0 = og*4, pxb = pg*6;
    unsigned long long acc[4][3];
    #pragma unroll
    for (int i = 0; i < 4; i++) {
        float bb = bs[o0 + i];
        unsigned long long p = pk2(bb, bb);
        acc[i][0] = p; acc[i][1] = p; acc[i][2] = p;
    }
    #pragma unroll 4
    for (int k = 0; k < 128; k++) {
        float4 w4 = *(const float4*)(s_w + k*64 + o0);
        unsigned long long w0 = pk2(w4.x, w4.x), wA = pk2(w4.y, w4.y);
        unsigned long long w2 = pk2(w4.z, w4.z), w3 = pk2(w4.w, w4.w);
        unsigned long long m0 = *(const unsigned long long*)(s_m + k*96 + pxb);
        unsigned long long m1 = *(const unsigned long long*)(s_m + k*96 + pxb + 2);
        unsigned long long m2 = *(const unsigned long long*)(s_m + k*96 + pxb + 4);
        fma2(acc[0][0], w0, m0); fma2(acc[0][1], w0, m1); fma2(acc[0][2], w0, m2);
        fma2(acc[1][0], wA, m0); fma2(acc[1][1], wA, m1); fma2(acc[1][2], wA, m2);
        fma2(acc[2][0], w2, m0); fma2(acc[2][1], w2, m1); fma2(acc[2][2], w2, m2);
        fma2(acc[3][0], w3, m0); fma2(acc[3][1], w3, m1); fma2(acc[3][2], w3, m2);
    }
    float* ob = out + (b*260 + 68 + scale*64 + o0)*HW + y*192 + px0 + pxb;
    #pragma unroll
    for (int i = 0; i < 4; i++) {
        float* op = ob + i*HW;
        *(unsigned long long*)(op)     = acc[i][0];
        *(unsigned long long*)(op + 2) = acc[i][1];
        *(unsigned long long*)(op + 4) = acc[i][2];
    }
}

// ============================================================================
extern "C" void kernel_launch(void* const* d_in, const int* in_sizes, int n_in,
                              void* d_out, int out_size)
{
    const float* feature = (const float*)d_in[0];
    const float* extra   = (const float*)d_in[1];
    const float* w_ctx   = (const float*)d_in[2];
    const float* b_ctx   = (const float*)d_in[3];
    const float* w1      = (const float*)d_in[4];
    const float* b1      = (const float*)d_in[5];
    const float* ws0     = (const float*)d_in[6];
    const float* bs0     = (const float*)d_in[7];
    const float* ws1     = (const float*)d_in[8];
    const float* bs1     = (const float*)d_in[9];
    const float* ws2     = (const float*)d_in[10];
    const float* bs2     = (const float*)d_in[11];
    float* out = (float*)d_out;

    cudaFuncSetAttribute(k1_kernel, cudaFuncAttributeMaxDynamicSharedMemorySize, 96256);
    cudaFuncSetAttribute(k4_kernel, cudaFuncAttributeMaxDynamicSharedMemorySize, 90112);

    k1_kernel<<<dim3(192, 6), 288, 96256>>>(feature, extra, w_ctx, b_ctx, w1, b1, out);
    k2_kernel<<<9216, 256>>>();
    k3_kernel<<<dim3(384, 2), 224>>>();
    k4_kernel<<<dim3(2, 192, 18), 256, 90112>>>(ws0, bs0, ws1, bs1, ws2, bs2, out);
}